// round 5
// baseline (speedup 1.0000x reference)
#include <cuda_runtime.h>
#include <cuda_bf16.h>
#include <cstdint>
#include <math.h>

// Shapes (fixed)
constexpr int NROW = 128;
constexpr int DDIM = 512;
constexpr int CDIM = 8192;
constexpr int NQ   = 32768;

// ---------------- device scratch ----------------
__device__ __align__(16) float g_s1[(size_t)NROW * NQ];
__device__ __align__(16) float g_s2[(size_t)NROW * NQ];
__device__ __align__(16) unsigned short g_a1h[NROW * DDIM];
__device__ __align__(16) unsigned short g_a1l[NROW * DDIM];
__device__ __align__(16) unsigned short g_a2h[NROW * CDIM];
__device__ __align__(16) unsigned short g_a2l[NROW * CDIM];
__device__ int   g_qlab[NQ];
__device__ float g_part[256 * 8];     // per (row, half): m1,l1,m2,l2,sw,s1w,s2w,cnt

// ---------------- small helpers ----------------
__device__ __forceinline__ uint32_t smem_u32(const void* p) {
    uint32_t a;
    asm("{ .reg .u64 t; cvta.to.shared.u64 t, %1; cvt.u32.u64 %0, t; }" : "=r"(a) : "l"(p));
    return a;
}
__device__ __forceinline__ void ldm4(uint32_t* r, uint32_t addr) {
    asm volatile("ldmatrix.sync.aligned.m8n8.x4.shared.b16 {%0,%1,%2,%3}, [%4];"
                 : "=r"(r[0]), "=r"(r[1]), "=r"(r[2]), "=r"(r[3]) : "r"(addr));
}
__device__ __forceinline__ void mma_bf16(float* d, const uint32_t* a, const uint32_t* b) {
    asm volatile(
        "mma.sync.aligned.m16n8k16.row.col.f32.bf16.bf16.f32 "
        "{%0,%1,%2,%3}, {%4,%5,%6,%7}, {%8,%9}, {%0,%1,%2,%3};"
        : "+f"(d[0]), "+f"(d[1]), "+f"(d[2]), "+f"(d[3])
        : "r"(a[0]), "r"(a[1]), "r"(a[2]), "r"(a[3]), "r"(b[0]), "r"(b[1]));
}
#define CP16(saddr, gptr) \
    asm volatile("cp.async.ca.shared.global [%0], [%1], 16;" :: "r"(saddr), "l"(gptr))
#define CP_COMMIT() asm volatile("cp.async.commit_group;" ::: "memory")
#define CP_WAIT0()  asm volatile("cp.async.wait_group 0;" ::: "memory")

// ---------------- kernel: normalize new_embeds + split to bf16 hi/lo ----------------
__global__ void normalize_split(const float* __restrict__ x) {
    int i = blockIdx.x, tid = threadIdx.x;           // 128 threads
    const float* xr = x + (size_t)i * DDIM;
    float s = 0.f;
    for (int d = tid; d < DDIM; d += 128) { float v = xr[d]; s += v * v; }
    for (int o = 16; o; o >>= 1) s += __shfl_down_sync(0xffffffffu, s, o);
    __shared__ float sh[4];
    if ((tid & 31) == 0) sh[tid >> 5] = s;
    __syncthreads();
    __shared__ float invs;
    if (tid == 0) invs = 1.0f / fmaxf(sqrtf(sh[0] + sh[1] + sh[2] + sh[3]), 1e-12f);
    __syncthreads();
    float iv = invs;
    for (int d = tid; d < DDIM; d += 128) {
        float v = xr[d] * iv;
        uint32_t b = __float_as_uint(v);
        float hi = __uint_as_float(b & 0xffff0000u);
        g_a1h[i * DDIM + d] = (unsigned short)(b >> 16);
        g_a1l[i * DDIM + d] = __bfloat16_as_ushort(__float2bfloat16_rn(v - hi));
    }
}

// ---------------- kernel: split new_logits to bf16 hi/lo ----------------
__global__ void split_logits(const float* __restrict__ x) {
    int idx = (blockIdx.x * blockDim.x + threadIdx.x) * 4;   // over 128*8192
    float4 v = *(const float4*)(x + idx);
    uint32_t bx = __float_as_uint(v.x), by = __float_as_uint(v.y);
    uint32_t bz = __float_as_uint(v.z), bw = __float_as_uint(v.w);
    uint2 hi;
    hi.x = __byte_perm(bx, by, 0x7632);
    hi.y = __byte_perm(bz, bw, 0x7632);
    *(uint2*)(g_a2h + idx) = hi;
    __nv_bfloat162 p0 = __floats2bfloat162_rn(v.x - __uint_as_float(bx & 0xffff0000u),
                                              v.y - __uint_as_float(by & 0xffff0000u));
    __nv_bfloat162 p1 = __floats2bfloat162_rn(v.z - __uint_as_float(bz & 0xffff0000u),
                                              v.w - __uint_as_float(bw & 0xffff0000u));
    uint2 lo; lo.x = *(uint32_t*)&p0; lo.y = *(uint32_t*)&p1;
    *(uint2*)(g_a2l + idx) = lo;
}

// ---------------- kernel: updated queue labels ----------------
__global__ void build_qlab(const int* __restrict__ ql, const int* __restrict__ labels,
                           const int* __restrict__ hdrp) {
    int j = blockIdx.x * blockDim.x + threadIdx.x;
    int hdr = *hdrp;
    int r = (j - hdr) & (NQ - 1);
    g_qlab[j] = (r < NROW) ? labels[r] : ql[j];
}

// ---------------- mma.sync bf16-split GEMM (overlapped pipeline) ----------------
// CTA tile 128x128, BK=32; 8 warps (4M x 2N), warp tile 32x64.
// A (bf16 hi/lo in GMEM): cp.async, double-buffered, distance 1.
// B (fp32 queue rows):     cp.async -> Bf32 (double, distance 2),
//                          converted to Bb16 hi/lo (double) OVERLAPPED with compute.
// One __syncthreads per chunk.
constexpr int BPAD   = 80;                 // bf16 tile row stride (conflict-free ldmatrix)
constexpr int SZ_AT  = 128 * BPAD;         // 10240 (one hi or lo tile)
constexpr int SZ_AST = 2 * SZ_AT;          // 20480 (hi+lo per stage)
constexpr int SZ_BF  = 128 * 128;          // 16384 (fp32 stage, 128B rows, XOR-swizzled)
constexpr int O_A    = 0;                  // [2 stages x 20480]
constexpr int O_B16  = 2 * SZ_AST;         // 40960 [2 stages x 20480]
constexpr int O_BF   = O_B16 + 2 * SZ_AST; // 81920 [2 stages x 16384]
constexpr int GEMM_SMEM = O_BF + 2 * SZ_BF;// 114688 (112KB) -> 2 CTAs/SM

__global__ __launch_bounds__(256, 2) void gemm_mma(
    const unsigned short* __restrict__ Ah,   // [128 x K] bf16 hi
    const unsigned short* __restrict__ Al,   // [128 x K] bf16 lo
    const float* __restrict__ Bq,            // [NQ x K]
    const float* __restrict__ Bold,          // [128 x K]
    const int* __restrict__ hdrp,
    float* __restrict__ out,                 // [128 x NQ]
    int K)
{
    extern __shared__ char smem[];
    const uint32_t sb = smem_u32(smem);
    const int tid = threadIdx.x, lane = tid & 31, wid = tid >> 5;
    const int wm = wid >> 1, wn = wid & 1;
    const int n0 = blockIdx.x * 128;
    const int nchunks = K >> 5;

    // B gmem row with circular-queue redirect; 2 threads per row (seg = 64B half)
    const int rb = tid >> 1, seg = tid & 1;
    const int hdr = *hdrp;
    const int j = n0 + rb;
    const int r = (j - hdr) & (NQ - 1);
    const char* gB = (const char*)((r < NROW) ? (Bold + (size_t)r * K)
                                              : (Bq + (size_t)j * K));
    const int rm = rb & 3;                 // 16B-block XOR swizzle key for Bf32

    // A: 2 threads per row, 32B each (hi and lo)
    const int arow = tid >> 1;
    const int acol = (tid & 1) * 32;
    const char* gAh = (const char*)Ah + (size_t)arow * K * 2 + acol;
    const char* gAl = (const char*)Al + (size_t)arow * K * 2 + acol;
    const uint32_t sA = sb + O_A + arow * BPAD + acol;

    // ldmatrix lane addressing
    const int g = lane >> 3, lr = lane & 7;
    const uint32_t aRowOff = (uint32_t)(wm * 32 + (g & 1) * 8 + lr) * BPAD + (g >> 1) * 16;
    const uint32_t bRowOff = (uint32_t)(wn * 64 + (g >> 1) * 8 + lr) * BPAD + (g & 1) * 16;

    float acc[2][8][4];
#pragma unroll
    for (int mt = 0; mt < 2; mt++)
#pragma unroll
        for (int nt = 0; nt < 8; nt++)
#pragma unroll
            for (int u = 0; u < 4; u++) acc[mt][nt][u] = 0.f;

    // cp.async A chunk c into stage st
    auto cpA = [&](int c, int st) {
        const char* s0 = gAh + (size_t)c * 64;
        const char* s1 = gAl + (size_t)c * 64;
        uint32_t d0 = sA + st * SZ_AST;            // hi
        uint32_t d1 = d0 + SZ_AT;                  // lo
        CP16(d0, s0); CP16(d0 + 16, s0 + 16);
        CP16(d1, s1); CP16(d1 + 16, s1 + 16);
    };
    // cp.async B fp32 chunk c into stage (c&1), XOR-swizzled 16B blocks
    auto cpB = [&](int c) {
        const char* s = gB + (size_t)c * 128 + seg * 64;
        uint32_t drow = sb + O_BF + (c & 1) * SZ_BF + rb * 128;
#pragma unroll
        for (int i = 0; i < 4; i++)
            CP16(drow + (((seg * 4 + i) ^ rm) << 4), s + i * 16);
    };
    // convert fp32 stage ts (chunk value irrelevant) -> bf16 tiles stage ts
    auto convertB = [&](int ts) {
        const char* base = smem + O_BF + ts * SZ_BF + rb * 128;
        float4 x0 = *(const float4*)(base + (((seg * 4 + 0) ^ rm) << 4));
        float4 x1 = *(const float4*)(base + (((seg * 4 + 1) ^ rm) << 4));
        float4 x2 = *(const float4*)(base + (((seg * 4 + 2) ^ rm) << 4));
        float4 x3 = *(const float4*)(base + (((seg * 4 + 3) ^ rm) << 4));
        char* dh = smem + O_B16 + ts * SZ_AST + rb * BPAD + seg * 32;
        char* dl = dh + SZ_AT;
        float4 xs[4] = {x0, x1, x2, x3};
#pragma unroll
        for (int h = 0; h < 2; h++) {
            float4 x = xs[2 * h], y = xs[2 * h + 1];
            uint32_t bxx = __float_as_uint(x.x), bxy = __float_as_uint(x.y);
            uint32_t bxz = __float_as_uint(x.z), bxw = __float_as_uint(x.w);
            uint32_t byx = __float_as_uint(y.x), byy = __float_as_uint(y.y);
            uint32_t byz = __float_as_uint(y.z), byw = __float_as_uint(y.w);
            uint4 hi;
            hi.x = __byte_perm(bxx, bxy, 0x7632);
            hi.y = __byte_perm(bxz, bxw, 0x7632);
            hi.z = __byte_perm(byx, byy, 0x7632);
            hi.w = __byte_perm(byz, byw, 0x7632);
            __nv_bfloat162 l0 = __floats2bfloat162_rn(x.x - __uint_as_float(bxx & 0xffff0000u),
                                                      x.y - __uint_as_float(bxy & 0xffff0000u));
            __nv_bfloat162 l1 = __floats2bfloat162_rn(x.z - __uint_as_float(bxz & 0xffff0000u),
                                                      x.w - __uint_as_float(bxw & 0xffff0000u));
            __nv_bfloat162 l2 = __floats2bfloat162_rn(y.x - __uint_as_float(byx & 0xffff0000u),
                                                      y.y - __uint_as_float(byy & 0xffff0000u));
            __nv_bfloat162 l3 = __floats2bfloat162_rn(y.z - __uint_as_float(byz & 0xffff0000u),
                                                      y.w - __uint_as_float(byw & 0xffff0000u));
            uint4 lo;
            lo.x = *(uint32_t*)&l0; lo.y = *(uint32_t*)&l1;
            lo.z = *(uint32_t*)&l2; lo.w = *(uint32_t*)&l3;
            *(uint4*)(dh + h * 16) = hi;
            *(uint4*)(dl + h * 16) = lo;
        }
    };

    auto compute = [&](int st) {
        const uint32_t bA0 = sb + O_A + st * SZ_AST + aRowOff;          // A hi
        const uint32_t bA1 = bA0 + SZ_AT;                               // A lo
        const uint32_t bBH = sb + O_B16 + st * SZ_AST + bRowOff;        // B hi
        const uint32_t bBL = bBH + SZ_AT;                               // B lo
#pragma unroll
        for (int ks = 0; ks < 2; ks++) {
            uint32_t a0[2][4], a1[2][4], bh[4][4], bl[4][4];
            ldm4(a0[0], bA0 + ks * 32);
            ldm4(a0[1], bA0 + 16 * BPAD + ks * 32);
#pragma unroll
            for (int p = 0; p < 4; p++) ldm4(bh[p], bBH + p * 16 * BPAD + ks * 32);
            ldm4(a1[0], bA1 + ks * 32);
            ldm4(a1[1], bA1 + 16 * BPAD + ks * 32);
#pragma unroll
            for (int mt = 0; mt < 2; mt++)
#pragma unroll
                for (int nt = 0; nt < 8; nt++)
                    mma_bf16(acc[mt][nt], a0[mt], &bh[nt >> 1][(nt & 1) * 2]);
#pragma unroll
            for (int p = 0; p < 4; p++) ldm4(bl[p], bBL + p * 16 * BPAD + ks * 32);
#pragma unroll
            for (int mt = 0; mt < 2; mt++)
#pragma unroll
                for (int nt = 0; nt < 8; nt++)
                    mma_bf16(acc[mt][nt], a1[mt], &bh[nt >> 1][(nt & 1) * 2]);
#pragma unroll
            for (int mt = 0; mt < 2; mt++)
#pragma unroll
                for (int nt = 0; nt < 8; nt++)
                    mma_bf16(acc[mt][nt], a0[mt], &bl[nt >> 1][(nt & 1) * 2]);
        }
    };

    // ---- prologue: A0, Bf32(0), Bf32(1); convert chunk 0 ----
    cpA(0, 0);
    cpB(0);
    if (1 < nchunks) cpB(1);
    CP_COMMIT();
    CP_WAIT0();
    __syncthreads();
    convertB(0);
    __syncthreads();

    // ---- main loop: one barrier per chunk; convert overlaps compute ----
    for (int c = 0; c < nchunks; c++) {
        const int st = c & 1;
        if (c + 1 < nchunks) cpA(c + 1, st ^ 1);
        if (c + 2 < nchunks) cpB(c + 2);
        CP_COMMIT();
        if (c + 1 < nchunks) convertB(st ^ 1);   // chunk c+1 (fp32 landed last iter)
        compute(st);
        CP_WAIT0();
        __syncthreads();
    }

    // ---- epilogue ----
    const int qr = lane >> 2, qc = (lane & 3) * 2;
#pragma unroll
    for (int mt = 0; mt < 2; mt++) {
        const int row = wm * 32 + mt * 16 + qr;
#pragma unroll
        for (int nt = 0; nt < 8; nt++) {
            const int col = n0 + wn * 64 + nt * 8 + qc;
            float2 v0; v0.x = acc[mt][nt][0]; v0.y = acc[mt][nt][1];
            float2 v1; v1.x = acc[mt][nt][2]; v1.y = acc[mt][nt][3];
            *(float2*)(out + (size_t)row * NQ + col) = v0;
            *(float2*)(out + (size_t)(row + 8) * NQ + col) = v1;
        }
    }
}

// ---------------- per-row reduction: 2 blocks per row (half-Q each) ----------------
__global__ __launch_bounds__(256) void row_reduce(
    const float* __restrict__ old_embeds, const float* __restrict__ feat_queue,
    const int* __restrict__ labels, const int* __restrict__ hdrp)
{
    const int i = blockIdx.x >> 1, half = blockIdx.x & 1, tid = threadIdx.x;
    const int lbl = labels[i];
    const int hdr = *hdrp;
    const int j0 = half * (NQ / 2);
    const float4* s1r = (const float4*)(g_s1 + (size_t)i * NQ + j0);
    const float4* s2r = (const float4*)(g_s2 + (size_t)i * NQ + j0);
    const int4*   ql4 = (const int4*)(g_qlab + j0);
    const float* oei = old_embeds + (size_t)i * DDIM;
    constexpr int NV = (NQ / 2) / 4;

    float m1 = -INFINITY, m2 = -INFINITY;
    for (int v = tid; v < NV; v += 256) {
        float4 a = s1r[v], b = s2r[v];
        m1 = fmaxf(fmaxf(fmaxf(m1, a.x), fmaxf(a.y, a.z)), a.w);
        m2 = fmaxf(fmaxf(fmaxf(m2, b.x), fmaxf(b.y, b.z)), b.w);
    }
    for (int o = 16; o; o >>= 1) {
        m1 = fmaxf(m1, __shfl_xor_sync(0xffffffffu, m1, o));
        m2 = fmaxf(m2, __shfl_xor_sync(0xffffffffu, m2, o));
    }
    __shared__ float shm1[8], shm2[8];
    if ((tid & 31) == 0) { shm1[tid >> 5] = m1; shm2[tid >> 5] = m2; }
    __syncthreads();
    float M1 = shm1[0], M2 = shm2[0];
    for (int w = 1; w < 8; w++) { M1 = fmaxf(M1, shm1[w]); M2 = fmaxf(M2, shm2[w]); }

    float l1 = 0.f, l2 = 0.f, sw = 0.f, s1w = 0.f, s2w = 0.f, cnt = 0.f;
    for (int v = tid; v < NV; v += 256) {
        float4 a = s1r[v], b = s2r[v];
        l1 += __expf(a.x - M1) + __expf(a.y - M1) + __expf(a.z - M1) + __expf(a.w - M1);
        l2 += __expf(b.x - M2) + __expf(b.y - M2) + __expf(b.z - M2) + __expf(b.w - M2);
        int4 q = ql4[v];
        if (q.x == lbl || q.y == lbl || q.z == lbl || q.w == lbl) {
            const float va[4] = {a.x, a.y, a.z, a.w};
            const float vb[4] = {b.x, b.y, b.z, b.w};
            const int   qq[4] = {q.x, q.y, q.z, q.w};
#pragma unroll
            for (int e = 0; e < 4; e++) {
                if (qq[e] != lbl) continue;
                int jj = j0 + v * 4 + e;
                int r = (jj - hdr) & (NQ - 1);
                const float* frow = (r < NROW) ? (old_embeds + (size_t)r * DDIM)
                                               : (feat_queue + (size_t)jj * DDIM);
                float dot = 0.f;
#pragma unroll 8
                for (int d = 0; d < DDIM; d++) dot = fmaf(oei[d], frow[d], dot);
                float w = 0.5f * (dot + 1.0f);
                sw += w; s1w += w * va[e]; s2w += w * vb[e]; cnt += 1.f;
            }
        }
    }
    for (int o = 16; o; o >>= 1) {
        l1  += __shfl_down_sync(0xffffffffu, l1, o);
        l2  += __shfl_down_sync(0xffffffffu, l2, o);
        sw  += __shfl_down_sync(0xffffffffu, sw, o);
        s1w += __shfl_down_sync(0xffffffffu, s1w, o);
        s2w += __shfl_down_sync(0xffffffffu, s2w, o);
        cnt += __shfl_down_sync(0xffffffffu, cnt, o);
    }
    __shared__ float shl1[8], shl2[8], shsw[8], shs1[8], shs2[8], shc[8];
    if ((tid & 31) == 0) {
        int w = tid >> 5;
        shl1[w] = l1; shl2[w] = l2; shsw[w] = sw; shs1[w] = s1w; shs2[w] = s2w; shc[w] = cnt;
    }
    __syncthreads();
    if (tid == 0) {
        float L1 = 0, L2 = 0, SW = 0, S1 = 0, S2 = 0, CN = 0;
        for (int w = 0; w < 8; w++) {
            L1 += shl1[w]; L2 += shl2[w]; SW += shsw[w];
            S1 += shs1[w]; S2 += shs2[w]; CN += shc[w];
        }
        float* p = g_part + blockIdx.x * 8;
        p[0] = M1; p[1] = L1; p[2] = M2; p[3] = L2;
        p[4] = SW; p[5] = S1; p[6] = S2; p[7] = CN;
    }
}

// ---------------- finalize ----------------
__global__ void finalize(float* __restrict__ out) {
    int tid = threadIdx.x;   // 128 threads, one row each
    const float* pa = g_part + (2 * tid) * 8;
    const float* pb = g_part + (2 * tid + 1) * 8;
    float M1 = fmaxf(pa[0], pb[0]);
    float L1 = pa[1] * __expf(pa[0] - M1) + pb[1] * __expf(pb[0] - M1);
    float M2 = fmaxf(pa[2], pb[2]);
    float L2 = pa[3] * __expf(pa[2] - M2) + pb[3] * __expf(pb[2] - M2);
    float SW = pa[4] + pb[4];
    float S1 = pa[5] + pb[5];
    float S2 = pa[6] + pb[6];
    float CN = pa[7] + pb[7];
    float lse1 = M1 + logf(L1);
    float lse2 = M2 + logf(L2);
    float ic = 1.0f / CN;
    float t1 = (S1 - lse1 * SW) * ic;
    float t2 = (S2 - lse2 * SW) * ic;
    for (int o = 16; o; o >>= 1) {
        t1 += __shfl_down_sync(0xffffffffu, t1, o);
        t2 += __shfl_down_sync(0xffffffffu, t2, o);
    }
    __shared__ float sh1[4], sh2[4];
    if ((tid & 31) == 0) { sh1[tid >> 5] = t1; sh2[tid >> 5] = t2; }
    __syncthreads();
    if (tid == 0) {
        out[0] = -(sh1[0] + sh1[1] + sh1[2] + sh1[3]) / (float)NROW;
        out[1] = -(sh2[0] + sh2[1] + sh2[2] + sh2[3]) / (float)NROW;
    }
}

// ---------------- launch ----------------
extern "C" void kernel_launch(void* const* d_in, const int* in_sizes, int n_in,
                              void* d_out, int out_size) {
    const float* old_embeds   = (const float*)d_in[0];
    const float* old_logits   = (const float*)d_in[1];
    const float* new_embeds   = (const float*)d_in[2];
    const float* new_logits   = (const float*)d_in[3];
    const int*   labels       = (const int*)d_in[4];
    const float* feat_queue   = (const float*)d_in[5];
    const float* logit_queue  = (const float*)d_in[6];
    const int*   queue_labels = (const int*)d_in[7];
    const int*   header       = (const int*)d_in[8];
    float* out = (float*)d_out;

    unsigned short *p_a1h, *p_a1l, *p_a2h, *p_a2l;
    float *p_s1, *p_s2;
    cudaGetSymbolAddress((void**)&p_a1h, g_a1h);
    cudaGetSymbolAddress((void**)&p_a1l, g_a1l);
    cudaGetSymbolAddress((void**)&p_a2h, g_a2h);
    cudaGetSymbolAddress((void**)&p_a2l, g_a2l);
    cudaGetSymbolAddress((void**)&p_s1, g_s1);
    cudaGetSymbolAddress((void**)&p_s2, g_s2);

    cudaFuncSetAttribute(gemm_mma, cudaFuncAttributeMaxDynamicSharedMemorySize, GEMM_SMEM);

    normalize_split<<<NROW, 128>>>(new_embeds);
    split_logits<<<(NROW * CDIM) / (256 * 4), 256>>>(new_logits);
    build_qlab<<<NQ / 256, 256>>>(queue_labels, labels, header);

    gemm_mma<<<NQ / 128, 256, GEMM_SMEM>>>(p_a1h, p_a1l, feat_queue, old_embeds,
                                           header, p_s1, DDIM);
    gemm_mma<<<NQ / 128, 256, GEMM_SMEM>>>(p_a2h, p_a2l, logit_queue, old_logits,
                                           header, p_s2, CDIM);

    row_reduce<<<2 * NROW, 256>>>(old_embeds, feat_queue, labels, header);
    finalize<<<1, 128>>>(out);
}

// round 6
// speedup vs baseline: 1.0042x; 1.0042x over previous
#include <cuda_runtime.h>
#include <cuda_bf16.h>
#include <cstdint>
#include <math.h>

// Shapes (fixed)
constexpr int NROW = 128;
constexpr int DDIM = 512;
constexpr int CDIM = 8192;
constexpr int NQ   = 32768;

// ---------------- device scratch ----------------
__device__ __align__(16) float g_s1[(size_t)NROW * NQ];
__device__ __align__(16) float g_s2[(size_t)NROW * NQ];
__device__ __align__(16) unsigned short g_a1h[NROW * DDIM];
__device__ __align__(16) unsigned short g_a1l[NROW * DDIM];
__device__ __align__(16) unsigned short g_a2h[NROW * CDIM];
__device__ __align__(16) unsigned short g_a2l[NROW * CDIM];
__device__ int   g_qlab[NQ];
__device__ float g_part[256 * 8];     // per (row, half): m1,l1,m2,l2,sw,s1w,s2w,cnt

// ---------------- small helpers ----------------
__device__ __forceinline__ uint32_t smem_u32(const void* p) {
    uint32_t a;
    asm("{ .reg .u64 t; cvta.to.shared.u64 t, %1; cvt.u32.u64 %0, t; }" : "=r"(a) : "l"(p));
    return a;
}
__device__ __forceinline__ void ldm4(uint32_t* r, uint32_t addr) {
    asm volatile("ldmatrix.sync.aligned.m8n8.x4.shared.b16 {%0,%1,%2,%3}, [%4];"
                 : "=r"(r[0]), "=r"(r[1]), "=r"(r[2]), "=r"(r[3]) : "r"(addr));
}
__device__ __forceinline__ void mma_bf16(float* d, const uint32_t* a, const uint32_t* b) {
    asm volatile(
        "mma.sync.aligned.m16n8k16.row.col.f32.bf16.bf16.f32 "
        "{%0,%1,%2,%3}, {%4,%5,%6,%7}, {%8,%9}, {%0,%1,%2,%3};"
        : "+f"(d[0]), "+f"(d[1]), "+f"(d[2]), "+f"(d[3])
        : "r"(a[0]), "r"(a[1]), "r"(a[2]), "r"(a[3]), "r"(b[0]), "r"(b[1]));
}
#define CP16(saddr, gptr) \
    asm volatile("cp.async.ca.shared.global [%0], [%1], 16;" :: "r"(saddr), "l"(gptr))
#define CP_COMMIT() asm volatile("cp.async.commit_group;" ::: "memory")
#define CP_WAIT0()  asm volatile("cp.async.wait_group 0;" ::: "memory")

// ---------------- kernel: normalize new_embeds + split to bf16 hi/lo ----------------
__global__ void normalize_split(const float* __restrict__ x) {
    int i = blockIdx.x, tid = threadIdx.x;           // 128 threads
    const float* xr = x + (size_t)i * DDIM;
    float s = 0.f;
    for (int d = tid; d < DDIM; d += 128) { float v = xr[d]; s += v * v; }
    for (int o = 16; o; o >>= 1) s += __shfl_down_sync(0xffffffffu, s, o);
    __shared__ float sh[4];
    if ((tid & 31) == 0) sh[tid >> 5] = s;
    __syncthreads();
    __shared__ float invs;
    if (tid == 0) invs = 1.0f / fmaxf(sqrtf(sh[0] + sh[1] + sh[2] + sh[3]), 1e-12f);
    __syncthreads();
    float iv = invs;
    for (int d = tid; d < DDIM; d += 128) {
        float v = xr[d] * iv;
        uint32_t b = __float_as_uint(v);
        float hi = __uint_as_float(b & 0xffff0000u);
        g_a1h[i * DDIM + d] = (unsigned short)(b >> 16);
        g_a1l[i * DDIM + d] = __bfloat16_as_ushort(__float2bfloat16_rn(v - hi));
    }
}

// ---------------- kernel: split new_logits to bf16 hi/lo ----------------
__global__ void split_logits(const float* __restrict__ x) {
    int idx = (blockIdx.x * blockDim.x + threadIdx.x) * 4;   // over 128*8192
    float4 v = *(const float4*)(x + idx);
    uint32_t bx = __float_as_uint(v.x), by = __float_as_uint(v.y);
    uint32_t bz = __float_as_uint(v.z), bw = __float_as_uint(v.w);
    uint2 hi;
    hi.x = __byte_perm(bx, by, 0x7632);
    hi.y = __byte_perm(bz, bw, 0x7632);
    *(uint2*)(g_a2h + idx) = hi;
    __nv_bfloat162 p0 = __floats2bfloat162_rn(v.x - __uint_as_float(bx & 0xffff0000u),
                                              v.y - __uint_as_float(by & 0xffff0000u));
    __nv_bfloat162 p1 = __floats2bfloat162_rn(v.z - __uint_as_float(bz & 0xffff0000u),
                                              v.w - __uint_as_float(bw & 0xffff0000u));
    uint2 lo; lo.x = *(uint32_t*)&p0; lo.y = *(uint32_t*)&p1;
    *(uint2*)(g_a2l + idx) = lo;
}

// ---------------- kernel: updated queue labels ----------------
__global__ void build_qlab(const int* __restrict__ ql, const int* __restrict__ labels,
                           const int* __restrict__ hdrp) {
    int j = blockIdx.x * blockDim.x + threadIdx.x;
    int hdr = *hdrp;
    int r = (j - hdr) & (NQ - 1);
    g_qlab[j] = (r < NROW) ? labels[r] : ql[j];
}

// ---------------- mma.sync bf16-split GEMM, 128x64 tile, 3 CTAs/SM ----------------
// CTA tile 128(M) x 64(N), BK=32; 8 warps (4M x 2N), warp tile 32x32.
// A (pre-split bf16 hi/lo, L2-resident): cp.async, double-buffered.
// B (fp32 queue rows, circular redirect): LDG -> regs -> convert -> STS (double-buffered).
// One __syncthreads per chunk; wait_group covers only the A cp.async (issued early).
constexpr int BPAD   = 80;                 // bf16 tile row stride (conflict-free ldmatrix)
constexpr int SZ_AT  = 128 * BPAD;         // 10240 (A hi or lo)
constexpr int SZ_AST = 2 * SZ_AT;          // 20480 per A stage (hi+lo)
constexpr int SZ_BT  = 64 * BPAD;          // 5120  (B hi or lo)
constexpr int SZ_BST = 2 * SZ_BT;          // 10240 per B stage
constexpr int O_A    = 0;                  // [2 stages]
constexpr int O_B16  = 2 * SZ_AST;         // 40960 [2 stages]
constexpr int GEMM_SMEM = O_B16 + 2 * SZ_BST;  // 61440 -> 3 CTAs/SM

__global__ __launch_bounds__(256, 3) void gemm_mma(
    const unsigned short* __restrict__ Ah,   // [128 x K] bf16 hi
    const unsigned short* __restrict__ Al,   // [128 x K] bf16 lo
    const float* __restrict__ Bq,            // [NQ x K]
    const float* __restrict__ Bold,          // [128 x K]
    const int* __restrict__ hdrp,
    float* __restrict__ out,                 // [128 x NQ]
    int K)
{
    extern __shared__ char smem[];
    const uint32_t sb = smem_u32(smem);
    const int tid = threadIdx.x, lane = tid & 31, wid = tid >> 5;
    const int wm = wid >> 1, wn = wid & 1;
    const int n0 = blockIdx.x * 64;
    const int nchunks = K >> 5;

    // B gmem row with circular-queue redirect; 4 threads per row, 8 fp32 each
    const int rb = tid >> 2, seg = tid & 3;
    const int hdr = *hdrp;
    const int j = n0 + rb;
    const int r = (j - hdr) & (NQ - 1);
    const float* gB = ((r < NROW) ? (Bold + (size_t)r * K) : (Bq + (size_t)j * K)) + seg * 8;

    // A: 2 threads per row, 32B (16 bf16) each, for hi and lo
    const int arow = tid >> 1;
    const int acol = (tid & 1) * 32;
    const char* gAh = (const char*)Ah + (size_t)arow * K * 2 + acol;
    const char* gAl = (const char*)Al + (size_t)arow * K * 2 + acol;
    const uint32_t sA = sb + O_A + arow * BPAD + acol;

    // ldmatrix lane addressing
    const int g = lane >> 3, lr = lane & 7;
    const uint32_t aRowOff = (uint32_t)(wm * 32 + (g & 1) * 8 + lr) * BPAD + (g >> 1) * 16;
    const uint32_t bRowOff = (uint32_t)(wn * 32 + (g >> 1) * 8 + lr) * BPAD + (g & 1) * 16;

    float acc[2][4][4];
#pragma unroll
    for (int mt = 0; mt < 2; mt++)
#pragma unroll
        for (int nt = 0; nt < 4; nt++)
#pragma unroll
            for (int u = 0; u < 4; u++) acc[mt][nt][u] = 0.f;

    auto cpA = [&](int c, int st) {
        const char* s0 = gAh + (size_t)c * 64;
        const char* s1 = gAl + (size_t)c * 64;
        uint32_t d0 = sA + st * SZ_AST;            // hi
        uint32_t d1 = d0 + SZ_AT;                  // lo
        CP16(d0, s0); CP16(d0 + 16, s0 + 16);
        CP16(d1, s1); CP16(d1 + 16, s1 + 16);
    };

    float4 bf0, bf1;                               // B staging regs (8 floats)
    auto loadB = [&](int c) {
        const float4* p = (const float4*)(gB + (size_t)c * 32);
        bf0 = __ldg(p); bf1 = __ldg(p + 1);
    };
    auto storeB = [&](int st) {
        uint32_t b0 = __float_as_uint(bf0.x), b1 = __float_as_uint(bf0.y);
        uint32_t b2 = __float_as_uint(bf0.z), b3 = __float_as_uint(bf0.w);
        uint32_t b4 = __float_as_uint(bf1.x), b5 = __float_as_uint(bf1.y);
        uint32_t b6 = __float_as_uint(bf1.z), b7 = __float_as_uint(bf1.w);
        uint4 hi;
        hi.x = __byte_perm(b0, b1, 0x7632);
        hi.y = __byte_perm(b2, b3, 0x7632);
        hi.z = __byte_perm(b4, b5, 0x7632);
        hi.w = __byte_perm(b6, b7, 0x7632);
        __nv_bfloat162 l0 = __floats2bfloat162_rn(bf0.x - __uint_as_float(b0 & 0xffff0000u),
                                                  bf0.y - __uint_as_float(b1 & 0xffff0000u));
        __nv_bfloat162 l1 = __floats2bfloat162_rn(bf0.z - __uint_as_float(b2 & 0xffff0000u),
                                                  bf0.w - __uint_as_float(b3 & 0xffff0000u));
        __nv_bfloat162 l2 = __floats2bfloat162_rn(bf1.x - __uint_as_float(b4 & 0xffff0000u),
                                                  bf1.y - __uint_as_float(b5 & 0xffff0000u));
        __nv_bfloat162 l3 = __floats2bfloat162_rn(bf1.z - __uint_as_float(b6 & 0xffff0000u),
                                                  bf1.w - __uint_as_float(b7 & 0xffff0000u));
        uint4 lo;
        lo.x = *(uint32_t*)&l0; lo.y = *(uint32_t*)&l1;
        lo.z = *(uint32_t*)&l2; lo.w = *(uint32_t*)&l3;
        char* dh = smem + O_B16 + st * SZ_BST + rb * BPAD + seg * 16;
        *(uint4*)dh = hi;
        *(uint4*)(dh + SZ_BT) = lo;
    };

    auto compute = [&](int st) {
        const uint32_t bA0 = sb + O_A + st * SZ_AST + aRowOff;      // A hi
        const uint32_t bA1 = bA0 + SZ_AT;                           // A lo
        const uint32_t bBH = sb + O_B16 + st * SZ_BST + bRowOff;    // B hi
        const uint32_t bBL = bBH + SZ_BT;                           // B lo
#pragma unroll
        for (int ks = 0; ks < 2; ks++) {
            uint32_t a0[2][4], a1[2][4], b[2][4];
            ldm4(a0[0], bA0 + ks * 32);
            ldm4(a0[1], bA0 + 16 * BPAD + ks * 32);
            ldm4(b[0], bBH + ks * 32);
            ldm4(b[1], bBH + 16 * BPAD + ks * 32);
            ldm4(a1[0], bA1 + ks * 32);
            ldm4(a1[1], bA1 + 16 * BPAD + ks * 32);
#pragma unroll
            for (int mt = 0; mt < 2; mt++)
#pragma unroll
                for (int nt = 0; nt < 4; nt++)
                    mma_bf16(acc[mt][nt], a0[mt], &b[nt >> 1][(nt & 1) * 2]);
#pragma unroll
            for (int mt = 0; mt < 2; mt++)
#pragma unroll
                for (int nt = 0; nt < 4; nt++)
                    mma_bf16(acc[mt][nt], a1[mt], &b[nt >> 1][(nt & 1) * 2]);
            ldm4(b[0], bBL + ks * 32);                // reuse b regs for B lo
            ldm4(b[1], bBL + 16 * BPAD + ks * 32);
#pragma unroll
            for (int mt = 0; mt < 2; mt++)
#pragma unroll
                for (int nt = 0; nt < 4; nt++)
                    mma_bf16(acc[mt][nt], a0[mt], &b[nt >> 1][(nt & 1) * 2]);
        }
    };

    // ---- prologue: chunk 0 ----
    loadB(0);
    cpA(0, 0);
    CP_COMMIT();
    storeB(0);
    CP_WAIT0();
    __syncthreads();

    // ---- main loop: one barrier per chunk ----
    for (int c = 0; c < nchunks; c++) {
        const int st = c & 1;
        const bool more = (c + 1 < nchunks);
        if (more) {
            cpA(c + 1, st ^ 1);
            CP_COMMIT();
            loadB(c + 1);          // LDG issued early; latency hidden under compute
        }
        compute(st);
        if (more) storeB(st ^ 1);  // convert after compute (regs now dead)
        CP_WAIT0();
        __syncthreads();
    }

    // ---- epilogue ----
    const int qr = lane >> 2, qc = (lane & 3) * 2;
#pragma unroll
    for (int mt = 0; mt < 2; mt++) {
        const int row = wm * 32 + mt * 16 + qr;
#pragma unroll
        for (int nt = 0; nt < 4; nt++) {
            const int col = n0 + wn * 32 + nt * 8 + qc;
            float2 v0; v0.x = acc[mt][nt][0]; v0.y = acc[mt][nt][1];
            float2 v1; v1.x = acc[mt][nt][2]; v1.y = acc[mt][nt][3];
            *(float2*)(out + (size_t)row * NQ + col) = v0;
            *(float2*)(out + (size_t)(row + 8) * NQ + col) = v1;
        }
    }
}

// ---------------- per-row reduction: 2 blocks per row (half-Q each) ----------------
__global__ __launch_bounds__(256) void row_reduce(
    const float* __restrict__ old_embeds, const float* __restrict__ feat_queue,
    const int* __restrict__ labels, const int* __restrict__ hdrp)
{
    const int i = blockIdx.x >> 1, half = blockIdx.x & 1, tid = threadIdx.x;
    const int lbl = labels[i];
    const int hdr = *hdrp;
    const int j0 = half * (NQ / 2);
    const float4* s1r = (const float4*)(g_s1 + (size_t)i * NQ + j0);
    const float4* s2r = (const float4*)(g_s2 + (size_t)i * NQ + j0);
    const int4*   ql4 = (const int4*)(g_qlab + j0);
    const float* oei = old_embeds + (size_t)i * DDIM;
    constexpr int NV = (NQ / 2) / 4;

    float m1 = -INFINITY, m2 = -INFINITY;
    for (int v = tid; v < NV; v += 256) {
        float4 a = s1r[v], b = s2r[v];
        m1 = fmaxf(fmaxf(fmaxf(m1, a.x), fmaxf(a.y, a.z)), a.w);
        m2 = fmaxf(fmaxf(fmaxf(m2, b.x), fmaxf(b.y, b.z)), b.w);
    }
    for (int o = 16; o; o >>= 1) {
        m1 = fmaxf(m1, __shfl_xor_sync(0xffffffffu, m1, o));
        m2 = fmaxf(m2, __shfl_xor_sync(0xffffffffu, m2, o));
    }
    __shared__ float shm1[8], shm2[8];
    if ((tid & 31) == 0) { shm1[tid >> 5] = m1; shm2[tid >> 5] = m2; }
    __syncthreads();
    float M1 = shm1[0], M2 = shm2[0];
    for (int w = 1; w < 8; w++) { M1 = fmaxf(M1, shm1[w]); M2 = fmaxf(M2, shm2[w]); }

    float l1 = 0.f, l2 = 0.f, sw = 0.f, s1w = 0.f, s2w = 0.f, cnt = 0.f;
    for (int v = tid; v < NV; v += 256) {
        float4 a = s1r[v], b = s2r[v];
        l1 += __expf(a.x - M1) + __expf(a.y - M1) + __expf(a.z - M1) + __expf(a.w - M1);
        l2 += __expf(b.x - M2) + __expf(b.y - M2) + __expf(b.z - M2) + __expf(b.w - M2);
        int4 q = ql4[v];
        if (q.x == lbl || q.y == lbl || q.z == lbl || q.w == lbl) {
            const float va[4] = {a.x, a.y, a.z, a.w};
            const float vb[4] = {b.x, b.y, b.z, b.w};
            const int   qq[4] = {q.x, q.y, q.z, q.w};
#pragma unroll
            for (int e = 0; e < 4; e++) {
                if (qq[e] != lbl) continue;
                int jj = j0 + v * 4 + e;
                int r = (jj - hdr) & (NQ - 1);
                const float* frow = (r < NROW) ? (old_embeds + (size_t)r * DDIM)
                                               : (feat_queue + (size_t)jj * DDIM);
                float dot = 0.f;
#pragma unroll 8
                for (int d = 0; d < DDIM; d++) dot = fmaf(oei[d], frow[d], dot);
                float w = 0.5f * (dot + 1.0f);
                sw += w; s1w += w * va[e]; s2w += w * vb[e]; cnt += 1.f;
            }
        }
    }
    for (int o = 16; o; o >>= 1) {
        l1  += __shfl_down_sync(0xffffffffu, l1, o);
        l2  += __shfl_down_sync(0xffffffffu, l2, o);
        sw  += __shfl_down_sync(0xffffffffu, sw, o);
        s1w += __shfl_down_sync(0xffffffffu, s1w, o);
        s2w += __shfl_down_sync(0xffffffffu, s2w, o);
        cnt += __shfl_down_sync(0xffffffffu, cnt, o);
    }
    __shared__ float shl1[8], shl2[8], shsw[8], shs1[8], shs2[8], shc[8];
    if ((tid & 31) == 0) {
        int w = tid >> 5;
        shl1[w] = l1; shl2[w] = l2; shsw[w] = sw; shs1[w] = s1w; shs2[w] = s2w; shc[w] = cnt;
    }
    __syncthreads();
    if (tid == 0) {
        float L1 = 0, L2 = 0, SW = 0, S1 = 0, S2 = 0, CN = 0;
        for (int w = 0; w < 8; w++) {
            L1 += shl1[w]; L2 += shl2[w]; SW += shsw[w];
            S1 += shs1[w]; S2 += shs2[w]; CN += shc[w];
        }
        float* p = g_part + blockIdx.x * 8;
        p[0] = M1; p[1] = L1; p[2] = M2; p[3] = L2;
        p[4] = SW; p[5] = S1; p[6] = S2; p[7] = CN;
    }
}

// ---------------- finalize ----------------
__global__ void finalize(float* __restrict__ out) {
    int tid = threadIdx.x;   // 128 threads, one row each
    const float* pa = g_part + (2 * tid) * 8;
    const float* pb = g_part + (2 * tid + 1) * 8;
    float M1 = fmaxf(pa[0], pb[0]);
    float L1 = pa[1] * __expf(pa[0] - M1) + pb[1] * __expf(pb[0] - M1);
    float M2 = fmaxf(pa[2], pb[2]);
    float L2 = pa[3] * __expf(pa[2] - M2) + pb[3] * __expf(pb[2] - M2);
    float SW = pa[4] + pb[4];
    float S1 = pa[5] + pb[5];
    float S2 = pa[6] + pb[6];
    float CN = pa[7] + pb[7];
    float lse1 = M1 + logf(L1);
    float lse2 = M2 + logf(L2);
    float ic = 1.0f / CN;
    float t1 = (S1 - lse1 * SW) * ic;
    float t2 = (S2 - lse2 * SW) * ic;
    for (int o = 16; o; o >>= 1) {
        t1 += __shfl_down_sync(0xffffffffu, t1, o);
        t2 += __shfl_down_sync(0xffffffffu, t2, o);
    }
    __shared__ float sh1[4], sh2[4];
    if ((tid & 31) == 0) { sh1[tid >> 5] = t1; sh2[tid >> 5] = t2; }
    __syncthreads();
    if (tid == 0) {
        out[0] = -(sh1[0] + sh1[1] + sh1[2] + sh1[3]) / (float)NROW;
        out[1] = -(sh2[0] + sh2[1] + sh2[2] + sh2[3]) / (float)NROW;
    }
}

// ---------------- launch ----------------
extern "C" void kernel_launch(void* const* d_in, const int* in_sizes, int n_in,
                              void* d_out, int out_size) {
    const float* old_embeds   = (const float*)d_in[0];
    const float* old_logits   = (const float*)d_in[1];
    const float* new_embeds   = (const float*)d_in[2];
    const float* new_logits   = (const float*)d_in[3];
    const int*   labels       = (const int*)d_in[4];
    const float* feat_queue   = (const float*)d_in[5];
    const float* logit_queue  = (const float*)d_in[6];
    const int*   queue_labels = (const int*)d_in[7];
    const int*   header       = (const int*)d_in[8];
    float* out = (float*)d_out;

    unsigned short *p_a1h, *p_a1l, *p_a2h, *p_a2l;
    float *p_s1, *p_s2;
    cudaGetSymbolAddress((void**)&p_a1h, g_a1h);
    cudaGetSymbolAddress((void**)&p_a1l, g_a1l);
    cudaGetSymbolAddress((void**)&p_a2h, g_a2h);
    cudaGetSymbolAddress((void**)&p_a2l, g_a2l);
    cudaGetSymbolAddress((void**)&p_s1, g_s1);
    cudaGetSymbolAddress((void**)&p_s2, g_s2);

    cudaFuncSetAttribute(gemm_mma, cudaFuncAttributeMaxDynamicSharedMemorySize, GEMM_SMEM);

    normalize_split<<<NROW, 128>>>(new_embeds);
    split_logits<<<(NROW * CDIM) / (256 * 4), 256>>>(new_logits);
    build_qlab<<<NQ / 256, 256>>>(queue_labels, labels, header);

    gemm_mma<<<NQ / 64, 256, GEMM_SMEM>>>(p_a1h, p_a1l, feat_queue, old_embeds,
                                          header, p_s1, DDIM);
    gemm_mma<<<NQ / 64, 256, GEMM_SMEM>>>(p_a2h, p_a2l, logit_queue, old_logits,
                                          header, p_s2, CDIM);

    row_reduce<<<2 * NROW, 256>>>(old_embeds, feat_queue, labels, header);
    finalize<<<1, 128>>>(out);
}

// round 7
// speedup vs baseline: 1.6252x; 1.6184x over previous
#include <cuda_runtime.h>
#include <cuda_fp16.h>
#include <cstdint>
#include <math.h>

// Shapes (fixed)
constexpr int NROW = 128;
constexpr int DDIM = 512;
constexpr int CDIM = 8192;
constexpr int NQ   = 32768;

// ---------------- device scratch ----------------
__device__ __align__(16) float g_s1[(size_t)NROW * NQ];
__device__ __align__(16) float g_s2[(size_t)NROW * NQ];
__device__ __align__(16) unsigned short g_a1h[NROW * DDIM];   // fp16 hi
__device__ __align__(16) unsigned short g_a1l[NROW * DDIM];   // fp16 lo
__device__ __align__(16) unsigned short g_a2h[NROW * CDIM];
__device__ __align__(16) unsigned short g_a2l[NROW * CDIM];
__device__ int   g_qlab[NQ];
__device__ float g_part[256 * 8];     // per (row, half): m1,l1,m2,l2,sw,s1w,s2w,cnt

// ---------------- small helpers ----------------
__device__ __forceinline__ uint32_t smem_u32(const void* p) {
    uint32_t a;
    asm("{ .reg .u64 t; cvta.to.shared.u64 t, %1; cvt.u32.u64 %0, t; }" : "=r"(a) : "l"(p));
    return a;
}
__device__ __forceinline__ void ldm4(uint32_t* r, uint32_t addr) {
    asm volatile("ldmatrix.sync.aligned.m8n8.x4.shared.b16 {%0,%1,%2,%3}, [%4];"
                 : "=r"(r[0]), "=r"(r[1]), "=r"(r[2]), "=r"(r[3]) : "r"(addr));
}
__device__ __forceinline__ void mma_f16(float* d, const uint32_t* a, const uint32_t* b) {
    asm volatile(
        "mma.sync.aligned.m16n8k16.row.col.f32.f16.f16.f32 "
        "{%0,%1,%2,%3}, {%4,%5,%6,%7}, {%8,%9}, {%0,%1,%2,%3};"
        : "+f"(d[0]), "+f"(d[1]), "+f"(d[2]), "+f"(d[3])
        : "r"(a[0]), "r"(a[1]), "r"(a[2]), "r"(a[3]), "r"(b[0]), "r"(b[1]));
}
#define CP16(saddr, gptr) \
    asm volatile("cp.async.ca.shared.global [%0], [%1], 16;" :: "r"(saddr), "l"(gptr))
#define CP_COMMIT() asm volatile("cp.async.commit_group;" ::: "memory")
#define CP_WAIT0()  asm volatile("cp.async.wait_group 0;" ::: "memory")

// ---------------- kernel: normalize new_embeds + split to fp16 hi/lo ----------------
__global__ void normalize_split(const float* __restrict__ x) {
    int i = blockIdx.x, tid = threadIdx.x;           // 128 threads
    const float* xr = x + (size_t)i * DDIM;
    float s = 0.f;
    for (int d = tid; d < DDIM; d += 128) { float v = xr[d]; s += v * v; }
    for (int o = 16; o; o >>= 1) s += __shfl_down_sync(0xffffffffu, s, o);
    __shared__ float sh[4];
    if ((tid & 31) == 0) sh[tid >> 5] = s;
    __syncthreads();
    __shared__ float invs;
    if (tid == 0) invs = 1.0f / fmaxf(sqrtf(sh[0] + sh[1] + sh[2] + sh[3]), 1e-12f);
    __syncthreads();
    float iv = invs;
    for (int d = tid; d < DDIM; d += 128) {
        float v = xr[d] * iv;
        __half hi = __float2half_rn(v);
        __half lo = __float2half_rn(v - __half2float(hi));
        g_a1h[i * DDIM + d] = __half_as_ushort(hi);
        g_a1l[i * DDIM + d] = __half_as_ushort(lo);
    }
}

// ---------------- kernel: split new_logits to fp16 hi/lo ----------------
__global__ void split_logits(const float* __restrict__ x) {
    int idx = (blockIdx.x * blockDim.x + threadIdx.x) * 4;   // over 128*8192
    float4 v = *(const float4*)(x + idx);
    __half h0 = __float2half_rn(v.x), h1 = __float2half_rn(v.y);
    __half h2 = __float2half_rn(v.z), h3 = __float2half_rn(v.w);
    __half l0 = __float2half_rn(v.x - __half2float(h0));
    __half l1 = __float2half_rn(v.y - __half2float(h1));
    __half l2 = __float2half_rn(v.z - __half2float(h2));
    __half l3 = __float2half_rn(v.w - __half2float(h3));
    unsigned short hs[4] = {__half_as_ushort(h0), __half_as_ushort(h1),
                            __half_as_ushort(h2), __half_as_ushort(h3)};
    unsigned short ls[4] = {__half_as_ushort(l0), __half_as_ushort(l1),
                            __half_as_ushort(l2), __half_as_ushort(l3)};
    *(uint2*)(g_a2h + idx) = *(const uint2*)hs;
    *(uint2*)(g_a2l + idx) = *(const uint2*)ls;
}

// ---------------- kernel: updated queue labels ----------------
__global__ void build_qlab(const int* __restrict__ ql, const int* __restrict__ labels,
                           const int* __restrict__ hdrp) {
    int j = blockIdx.x * blockDim.x + threadIdx.x;
    int hdr = *hdrp;
    int r = (j - hdr) & (NQ - 1);
    g_qlab[j] = (r < NROW) ? labels[r] : ql[j];
}

// ---------------- mma.sync fp16 A-split GEMM ----------------
// D = (Ahi + Alo) @ B_fp16; A pre-split fp16 hi/lo in GMEM; B fp32 rows -> fp16 RN.
// CTA tile 128x128, BK=32; 8 warps (4M x 2N), warp tile 32x64; 2 MMAs per fragment set.
constexpr int BPAD = 80;                 // row stride: 64B data + 16B pad (conflict-free)
constexpr int SZ_T = 128 * BPAD;         // 10240 per tile
constexpr int O_AH = 0;
constexpr int O_AL = SZ_T;               // 10240
constexpr int O_B  = 2 * SZ_T;           // 20480
constexpr int STG  = 3 * SZ_T;           // 30720 per stage
constexpr int GEMM_SMEM = 2 * STG;       // 61440 -> 2 CTAs/SM (and L1 room)

__global__ __launch_bounds__(256, 2) void gemm_mma(
    const unsigned short* __restrict__ Ah,   // [128 x K] fp16 hi
    const unsigned short* __restrict__ Al,   // [128 x K] fp16 lo
    const float* __restrict__ Bq,            // [NQ x K]
    const float* __restrict__ Bold,          // [128 x K]
    const int* __restrict__ hdrp,
    float* __restrict__ out,                 // [128 x NQ]
    int K)
{
    extern __shared__ char smem[];
    const uint32_t sb = smem_u32(smem);
    const int tid = threadIdx.x, lane = tid & 31, wid = tid >> 5;
    const int wm = wid >> 1, wn = wid & 1;
    const int n0 = blockIdx.x * 128;
    const int nchunks = K >> 5;

    // B gmem row with circular-queue redirect; 2 threads per row, 16 fp32 each
    const int rb = tid >> 1, seg = tid & 1;
    const int hdr = *hdrp;
    const int j = n0 + rb;
    const int r = (j - hdr) & (NQ - 1);
    const float* gB = ((r < NROW) ? (Bold + (size_t)r * K) : (Bq + (size_t)j * K)) + seg * 16;

    // A: 2 threads per row, 32B each (row = 64B of fp16), for hi and lo
    const int arow = tid >> 1;
    const int acol = (tid & 1) * 32;
    const char* gAh = (const char*)Ah + (size_t)arow * K * 2 + acol;
    const char* gAl = (const char*)Al + (size_t)arow * K * 2 + acol;
    const uint32_t sA = sb + arow * BPAD + acol;

    // ldmatrix lane addressing
    const int g = lane >> 3, lr = lane & 7;
    const uint32_t aRowOff = (uint32_t)(wm * 32 + (g & 1) * 8 + lr) * BPAD + (g >> 1) * 16;
    const uint32_t bRowOff = (uint32_t)(wn * 64 + (g >> 1) * 8 + lr) * BPAD + (g & 1) * 16;

    float acc[2][8][4];
#pragma unroll
    for (int mt = 0; mt < 2; mt++)
#pragma unroll
        for (int nt = 0; nt < 8; nt++)
#pragma unroll
            for (int u = 0; u < 4; u++) acc[mt][nt][u] = 0.f;

    auto cpA = [&](int c, int st) {
        const char* s0 = gAh + (size_t)c * 64;
        const char* s1 = gAl + (size_t)c * 64;
        uint32_t d0 = sA + st * STG + O_AH;
        uint32_t d1 = sA + st * STG + O_AL;
        CP16(d0, s0); CP16(d0 + 16, s0 + 16);
        CP16(d1, s1); CP16(d1 + 16, s1 + 16);
    };

    float4 f0, f1, f2, f3;                         // B staging (16 fp32)
    auto loadB = [&](int c) {
        const float4* p = (const float4*)(gB + (size_t)c * 32);
        f0 = __ldg(p); f1 = __ldg(p + 1); f2 = __ldg(p + 2); f3 = __ldg(p + 3);
    };
    auto storeB = [&](int st) {
        __half2 h0 = __floats2half2_rn(f0.x, f0.y);
        __half2 h1 = __floats2half2_rn(f0.z, f0.w);
        __half2 h2 = __floats2half2_rn(f1.x, f1.y);
        __half2 h3 = __floats2half2_rn(f1.z, f1.w);
        __half2 h4 = __floats2half2_rn(f2.x, f2.y);
        __half2 h5 = __floats2half2_rn(f2.z, f2.w);
        __half2 h6 = __floats2half2_rn(f3.x, f3.y);
        __half2 h7 = __floats2half2_rn(f3.z, f3.w);
        uint4 p0, p1;
        p0.x = *(uint32_t*)&h0; p0.y = *(uint32_t*)&h1;
        p0.z = *(uint32_t*)&h2; p0.w = *(uint32_t*)&h3;
        p1.x = *(uint32_t*)&h4; p1.y = *(uint32_t*)&h5;
        p1.z = *(uint32_t*)&h6; p1.w = *(uint32_t*)&h7;
        char* d = smem + st * STG + O_B + rb * BPAD + seg * 32;
        *(uint4*)d = p0;
        *(uint4*)(d + 16) = p1;
    };

    auto compute = [&](int st) {
        const uint32_t bA0 = sb + st * STG + O_AH + aRowOff;   // A hi
        const uint32_t bA1 = sb + st * STG + O_AL + aRowOff;   // A lo
        const uint32_t bB  = sb + st * STG + O_B  + bRowOff;   // B fp16
#pragma unroll
        for (int ks = 0; ks < 2; ks++) {
            uint32_t a0[2][4], a1[2][4], b[4][4];
            ldm4(a0[0], bA0 + ks * 32);
            ldm4(a0[1], bA0 + 16 * BPAD + ks * 32);
#pragma unroll
            for (int p = 0; p < 4; p++) ldm4(b[p], bB + p * 16 * BPAD + ks * 32);
            ldm4(a1[0], bA1 + ks * 32);
            ldm4(a1[1], bA1 + 16 * BPAD + ks * 32);
#pragma unroll
            for (int mt = 0; mt < 2; mt++)
#pragma unroll
                for (int nt = 0; nt < 8; nt++)
                    mma_f16(acc[mt][nt], a0[mt], &b[nt >> 1][(nt & 1) * 2]);
#pragma unroll
            for (int mt = 0; mt < 2; mt++)
#pragma unroll
                for (int nt = 0; nt < 8; nt++)
                    mma_f16(acc[mt][nt], a1[mt], &b[nt >> 1][(nt & 1) * 2]);
        }
    };

    // ---- prologue: chunk 0 ----
    loadB(0);
    cpA(0, 0);
    CP_COMMIT();
    storeB(0);
    CP_WAIT0();
    __syncthreads();

    // ---- main loop: one barrier per chunk ----
    for (int c = 0; c < nchunks; c++) {
        const int st = c & 1;
        const bool more = (c + 1 < nchunks);
        if (more) {
            cpA(c + 1, st ^ 1);
            CP_COMMIT();
            loadB(c + 1);          // LDG early, hidden under compute
        }
        compute(st);
        if (more) storeB(st ^ 1);  // convert+STS after compute
        CP_WAIT0();
        __syncthreads();
    }

    // ---- epilogue ----
    const int qr = lane >> 2, qc = (lane & 3) * 2;
#pragma unroll
    for (int mt = 0; mt < 2; mt++) {
        const int row = wm * 32 + mt * 16 + qr;
#pragma unroll
        for (int nt = 0; nt < 8; nt++) {
            const int col = n0 + wn * 64 + nt * 8 + qc;
            float2 v0; v0.x = acc[mt][nt][0]; v0.y = acc[mt][nt][1];
            float2 v1; v1.x = acc[mt][nt][2]; v1.y = acc[mt][nt][3];
            *(float2*)(out + (size_t)row * NQ + col) = v0;
            *(float2*)(out + (size_t)(row + 8) * NQ + col) = v1;
        }
    }
}

// ---------------- per-row reduction: 2 blocks per row (half-Q each) ----------------
__global__ __launch_bounds__(256) void row_reduce(
    const float* __restrict__ old_embeds, const float* __restrict__ feat_queue,
    const int* __restrict__ labels, const int* __restrict__ hdrp)
{
    const int i = blockIdx.x >> 1, half = blockIdx.x & 1, tid = threadIdx.x;
    const int lbl = labels[i];
    const int hdr = *hdrp;
    const int j0 = half * (NQ / 2);
    const float4* s1r = (const float4*)(g_s1 + (size_t)i * NQ + j0);
    const float4* s2r = (const float4*)(g_s2 + (size_t)i * NQ + j0);
    const int4*   ql4 = (const int4*)(g_qlab + j0);
    const float* oei = old_embeds + (size_t)i * DDIM;
    constexpr int NV = (NQ / 2) / 4;

    float m1 = -INFINITY, m2 = -INFINITY;
    for (int v = tid; v < NV; v += 256) {
        float4 a = s1r[v], b = s2r[v];
        m1 = fmaxf(fmaxf(fmaxf(m1, a.x), fmaxf(a.y, a.z)), a.w);
        m2 = fmaxf(fmaxf(fmaxf(m2, b.x), fmaxf(b.y, b.z)), b.w);
    }
    for (int o = 16; o; o >>= 1) {
        m1 = fmaxf(m1, __shfl_xor_sync(0xffffffffu, m1, o));
        m2 = fmaxf(m2, __shfl_xor_sync(0xffffffffu, m2, o));
    }
    __shared__ float shm1[8], shm2[8];
    if ((tid & 31) == 0) { shm1[tid >> 5] = m1; shm2[tid >> 5] = m2; }
    __syncthreads();
    float M1 = shm1[0], M2 = shm2[0];
    for (int w = 1; w < 8; w++) { M1 = fmaxf(M1, shm1[w]); M2 = fmaxf(M2, shm2[w]); }

    float l1 = 0.f, l2 = 0.f, sw = 0.f, s1w = 0.f, s2w = 0.f, cnt = 0.f;
    for (int v = tid; v < NV; v += 256) {
        float4 a = s1r[v], b = s2r[v];
        l1 += __expf(a.x - M1) + __expf(a.y - M1) + __expf(a.z - M1) + __expf(a.w - M1);
        l2 += __expf(b.x - M2) + __expf(b.y - M2) + __expf(b.z - M2) + __expf(b.w - M2);
        int4 q = ql4[v];
        if (q.x == lbl || q.y == lbl || q.z == lbl || q.w == lbl) {
            const float va[4] = {a.x, a.y, a.z, a.w};
            const float vb[4] = {b.x, b.y, b.z, b.w};
            const int   qq[4] = {q.x, q.y, q.z, q.w};
#pragma unroll
            for (int e = 0; e < 4; e++) {
                if (qq[e] != lbl) continue;
                int jj = j0 + v * 4 + e;
                int r = (jj - hdr) & (NQ - 1);
                const float* frow = (r < NROW) ? (old_embeds + (size_t)r * DDIM)
                                               : (feat_queue + (size_t)jj * DDIM);
                float dot = 0.f;
#pragma unroll 8
                for (int d = 0; d < DDIM; d++) dot = fmaf(oei[d], frow[d], dot);
                float w = 0.5f * (dot + 1.0f);
                sw += w; s1w += w * va[e]; s2w += w * vb[e]; cnt += 1.f;
            }
        }
    }
    for (int o = 16; o; o >>= 1) {
        l1  += __shfl_down_sync(0xffffffffu, l1, o);
        l2  += __shfl_down_sync(0xffffffffu, l2, o);
        sw  += __shfl_down_sync(0xffffffffu, sw, o);
        s1w += __shfl_down_sync(0xffffffffu, s1w, o);
        s2w += __shfl_down_sync(0xffffffffu, s2w, o);
        cnt += __shfl_down_sync(0xffffffffu, cnt, o);
    }
    __shared__ float shl1[8], shl2[8], shsw[8], shs1[8], shs2[8], shc[8];
    if ((tid & 31) == 0) {
        int w = tid >> 5;
        shl1[w] = l1; shl2[w] = l2; shsw[w] = sw; shs1[w] = s1w; shs2[w] = s2w; shc[w] = cnt;
    }
    __syncthreads();
    if (tid == 0) {
        float L1 = 0, L2 = 0, SW = 0, S1 = 0, S2 = 0, CN = 0;
        for (int w = 0; w < 8; w++) {
            L1 += shl1[w]; L2 += shl2[w]; SW += shsw[w];
            S1 += shs1[w]; S2 += shs2[w]; CN += shc[w];
        }
        float* p = g_part + blockIdx.x * 8;
        p[0] = M1; p[1] = L1; p[2] = M2; p[3] = L2;
        p[4] = SW; p[5] = S1; p[6] = S2; p[7] = CN;
    }
}

// ---------------- finalize ----------------
__global__ void finalize(float* __restrict__ out) {
    int tid = threadIdx.x;   // 128 threads, one row each
    const float* pa = g_part + (2 * tid) * 8;
    const float* pb = g_part + (2 * tid + 1) * 8;
    float M1 = fmaxf(pa[0], pb[0]);
    float L1 = pa[1] * __expf(pa[0] - M1) + pb[1] * __expf(pb[0] - M1);
    float M2 = fmaxf(pa[2], pb[2]);
    float L2 = pa[3] * __expf(pa[2] - M2) + pb[3] * __expf(pb[2] - M2);
    float SW = pa[4] + pb[4];
    float S1 = pa[5] + pb[5];
    float S2 = pa[6] + pb[6];
    float CN = pa[7] + pb[7];
    float lse1 = M1 + logf(L1);
    float lse2 = M2 + logf(L2);
    float ic = 1.0f / CN;
    float t1 = (S1 - lse1 * SW) * ic;
    float t2 = (S2 - lse2 * SW) * ic;
    for (int o = 16; o; o >>= 1) {
        t1 += __shfl_down_sync(0xffffffffu, t1, o);
        t2 += __shfl_down_sync(0xffffffffu, t2, o);
    }
    __shared__ float sh1[4], sh2[4];
    if ((tid & 31) == 0) { sh1[tid >> 5] = t1; sh2[tid >> 5] = t2; }
    __syncthreads();
    if (tid == 0) {
        out[0] = -(sh1[0] + sh1[1] + sh1[2] + sh1[3]) / (float)NROW;
        out[1] = -(sh2[0] + sh2[1] + sh2[2] + sh2[3]) / (float)NROW;
    }
}

// ---------------- launch ----------------
extern "C" void kernel_launch(void* const* d_in, const int* in_sizes, int n_in,
                              void* d_out, int out_size) {
    const float* old_embeds   = (const float*)d_in[0];
    const float* old_logits   = (const float*)d_in[1];
    const float* new_embeds   = (const float*)d_in[2];
    const float* new_logits   = (const float*)d_in[3];
    const int*   labels       = (const int*)d_in[4];
    const float* feat_queue   = (const float*)d_in[5];
    const float* logit_queue  = (const float*)d_in[6];
    const int*   queue_labels = (const int*)d_in[7];
    const int*   header       = (const int*)d_in[8];
    float* out = (float*)d_out;

    unsigned short *p_a1h, *p_a1l, *p_a2h, *p_a2l;
    float *p_s1, *p_s2;
    cudaGetSymbolAddress((void**)&p_a1h, g_a1h);
    cudaGetSymbolAddress((void**)&p_a1l, g_a1l);
    cudaGetSymbolAddress((void**)&p_a2h, g_a2h);
    cudaGetSymbolAddress((void**)&p_a2l, g_a2l);
    cudaGetSymbolAddress((void**)&p_s1, g_s1);
    cudaGetSymbolAddress((void**)&p_s2, g_s2);

    cudaFuncSetAttribute(gemm_mma, cudaFuncAttributeMaxDynamicSharedMemorySize, GEMM_SMEM);

    normalize_split<<<NROW, 128>>>(new_embeds);
    split_logits<<<(NROW * CDIM) / (256 * 4), 256>>>(new_logits);
    build_qlab<<<NQ / 256, 256>>>(queue_labels, labels, header);

    gemm_mma<<<NQ / 128, 256, GEMM_SMEM>>>(p_a1h, p_a1l, feat_queue, old_embeds,
                                           header, p_s1, DDIM);
    gemm_mma<<<NQ / 128, 256, GEMM_SMEM>>>(p_a2h, p_a2l, logit_queue, old_logits,
                                           header, p_s2, CDIM);

    row_reduce<<<2 * NROW, 256>>>(old_embeds, feat_queue, labels, header);
    finalize<<<1, 128>>>(out);
}

// round 8
// speedup vs baseline: 2.0494x; 1.2610x over previous
#include <cuda_runtime.h>
#include <cuda_fp16.h>
#include <cstdint>
#include <math.h>

// Shapes (fixed)
constexpr int NROW = 128;
constexpr int DDIM = 512;
constexpr int CDIM = 8192;
constexpr int NQ   = 32768;

// ---------------- device scratch ----------------
__device__ __align__(16) float g_s1[(size_t)NROW * NQ];
__device__ __align__(16) float g_s2[(size_t)NROW * NQ];
__device__ __align__(16) unsigned short g_a1[NROW * DDIM];   // fp16 normalized new_embeds
__device__ __align__(16) unsigned short g_a2[NROW * CDIM];   // fp16 new_logits
__device__ int   g_qlab[NQ];
__device__ float g_part[256 * 8];     // per (row, half): m1,l1,m2,l2,sw,s1w,s2w,cnt

// ---------------- small helpers ----------------
__device__ __forceinline__ uint32_t smem_u32(const void* p) {
    uint32_t a;
    asm("{ .reg .u64 t; cvta.to.shared.u64 t, %1; cvt.u32.u64 %0, t; }" : "=r"(a) : "l"(p));
    return a;
}
__device__ __forceinline__ void ldm4(uint32_t* r, uint32_t addr) {
    asm volatile("ldmatrix.sync.aligned.m8n8.x4.shared.b16 {%0,%1,%2,%3}, [%4];"
                 : "=r"(r[0]), "=r"(r[1]), "=r"(r[2]), "=r"(r[3]) : "r"(addr));
}
__device__ __forceinline__ void mma_f16(float* d, const uint32_t* a, const uint32_t* b) {
    asm volatile(
        "mma.sync.aligned.m16n8k16.row.col.f32.f16.f16.f32 "
        "{%0,%1,%2,%3}, {%4,%5,%6,%7}, {%8,%9}, {%0,%1,%2,%3};"
        : "+f"(d[0]), "+f"(d[1]), "+f"(d[2]), "+f"(d[3])
        : "r"(a[0]), "r"(a[1]), "r"(a[2]), "r"(a[3]), "r"(b[0]), "r"(b[1]));
}
#define CP16(saddr, gptr) \
    asm volatile("cp.async.ca.shared.global [%0], [%1], 16;" :: "r"(saddr), "l"(gptr))
#define CP_COMMIT() asm volatile("cp.async.commit_group;" ::: "memory")
#define CP_WAIT0()  asm volatile("cp.async.wait_group 0;" ::: "memory")

// ---------------- kernel: normalize new_embeds -> fp16 ----------------
__global__ void normalize_half(const float* __restrict__ x) {
    int i = blockIdx.x, tid = threadIdx.x;           // 128 threads
    const float* xr = x + (size_t)i * DDIM;
    float s = 0.f;
    for (int d = tid; d < DDIM; d += 128) { float v = xr[d]; s += v * v; }
    for (int o = 16; o; o >>= 1) s += __shfl_down_sync(0xffffffffu, s, o);
    __shared__ float sh[4];
    if ((tid & 31) == 0) sh[tid >> 5] = s;
    __syncthreads();
    __shared__ float invs;
    if (tid == 0) invs = 1.0f / fmaxf(sqrtf(sh[0] + sh[1] + sh[2] + sh[3]), 1e-12f);
    __syncthreads();
    float iv = invs;
    for (int d = tid; d < DDIM; d += 128)
        g_a1[i * DDIM + d] = __half_as_ushort(__float2half_rn(xr[d] * iv));
}

// ---------------- kernel: new_logits -> fp16 ----------------
__global__ void half_logits(const float* __restrict__ x) {
    int idx = (blockIdx.x * blockDim.x + threadIdx.x) * 4;   // over 128*8192
    float4 v = *(const float4*)(x + idx);
    __half2 h0 = __floats2half2_rn(v.x, v.y);
    __half2 h1 = __floats2half2_rn(v.z, v.w);
    uint2 p; p.x = *(uint32_t*)&h0; p.y = *(uint32_t*)&h1;
    *(uint2*)(g_a2 + idx) = p;
}

// ---------------- kernel: updated queue labels ----------------
__global__ void build_qlab(const int* __restrict__ ql, const int* __restrict__ labels,
                           const int* __restrict__ hdrp) {
    int j = blockIdx.x * blockDim.x + threadIdx.x;
    int hdr = *hdrp;
    int r = (j - hdr) & (NQ - 1);
    g_qlab[j] = (r < NROW) ? labels[r] : ql[j];
}

// ---------------- mma.sync fp16 GEMM (single precision-level) ----------------
// D = A_fp16 @ B_fp16^T; A pre-converted fp16 in GMEM; B fp32 rows -> fp16 RN on the fly.
// CTA tile 128x128, BK=32; 8 warps (4M x 2N), warp tile 32x64.
constexpr int BPAD = 80;                 // row stride: 64B data + 16B pad (conflict-free)
constexpr int SZ_T = 128 * BPAD;         // 10240 per tile
constexpr int O_A  = 0;
constexpr int O_B  = SZ_T;               // 10240
constexpr int STG  = 2 * SZ_T;           // 20480 per stage
constexpr int GEMM_SMEM = 2 * STG;       // 40960 -> 2 CTAs/SM with L1 headroom

__global__ __launch_bounds__(256, 2) void gemm_mma(
    const unsigned short* __restrict__ A,    // [128 x K] fp16
    const float* __restrict__ Bq,            // [NQ x K]
    const float* __restrict__ Bold,          // [128 x K]
    const int* __restrict__ hdrp,
    float* __restrict__ out,                 // [128 x NQ]
    int K)
{
    extern __shared__ char smem[];
    const uint32_t sb = smem_u32(smem);
    const int tid = threadIdx.x, lane = tid & 31, wid = tid >> 5;
    const int wm = wid >> 1, wn = wid & 1;
    const int n0 = blockIdx.x * 128;
    const int nchunks = K >> 5;

    // B gmem row with circular-queue redirect; 2 threads per row, 16 fp32 each
    const int rb = tid >> 1, seg = tid & 1;
    const int hdr = *hdrp;
    const int j = n0 + rb;
    const int r = (j - hdr) & (NQ - 1);
    const float* gB = ((r < NROW) ? (Bold + (size_t)r * K) : (Bq + (size_t)j * K)) + seg * 16;

    // A: 2 threads per row, 32B each (row = 64B of fp16)
    const int arow = tid >> 1;
    const int acol = (tid & 1) * 32;
    const char* gA = (const char*)A + (size_t)arow * K * 2 + acol;
    const uint32_t sA = sb + O_A + arow * BPAD + acol;

    // ldmatrix lane addressing
    const int g = lane >> 3, lr = lane & 7;
    const uint32_t aRowOff = (uint32_t)(wm * 32 + (g & 1) * 8 + lr) * BPAD + (g >> 1) * 16;
    const uint32_t bRowOff = (uint32_t)(wn * 64 + (g >> 1) * 8 + lr) * BPAD + (g & 1) * 16;

    float acc[2][8][4];
#pragma unroll
    for (int mt = 0; mt < 2; mt++)
#pragma unroll
        for (int nt = 0; nt < 8; nt++)
#pragma unroll
            for (int u = 0; u < 4; u++) acc[mt][nt][u] = 0.f;

    auto cpA = [&](int c, int st) {
        const char* s0 = gA + (size_t)c * 64;
        uint32_t d0 = sA + st * STG;
        CP16(d0, s0); CP16(d0 + 16, s0 + 16);
    };

    float4 f0, f1, f2, f3;                         // B staging (16 fp32)
    auto loadB = [&](int c) {
        const float4* p = (const float4*)(gB + (size_t)c * 32);
        f0 = __ldg(p); f1 = __ldg(p + 1); f2 = __ldg(p + 2); f3 = __ldg(p + 3);
    };
    auto storeB = [&](int st) {
        __half2 h0 = __floats2half2_rn(f0.x, f0.y);
        __half2 h1 = __floats2half2_rn(f0.z, f0.w);
        __half2 h2 = __floats2half2_rn(f1.x, f1.y);
        __half2 h3 = __floats2half2_rn(f1.z, f1.w);
        __half2 h4 = __floats2half2_rn(f2.x, f2.y);
        __half2 h5 = __floats2half2_rn(f2.z, f2.w);
        __half2 h6 = __floats2half2_rn(f3.x, f3.y);
        __half2 h7 = __floats2half2_rn(f3.z, f3.w);
        uint4 p0, p1;
        p0.x = *(uint32_t*)&h0; p0.y = *(uint32_t*)&h1;
        p0.z = *(uint32_t*)&h2; p0.w = *(uint32_t*)&h3;
        p1.x = *(uint32_t*)&h4; p1.y = *(uint32_t*)&h5;
        p1.z = *(uint32_t*)&h6; p1.w = *(uint32_t*)&h7;
        char* d = smem + st * STG + O_B + rb * BPAD + seg * 32;
        *(uint4*)d = p0;
        *(uint4*)(d + 16) = p1;
    };

    auto compute = [&](int st) {
        const uint32_t bA = sb + st * STG + O_A + aRowOff;
        const uint32_t bB = sb + st * STG + O_B + bRowOff;
#pragma unroll
        for (int ks = 0; ks < 2; ks++) {
            uint32_t a[2][4], b[4][4];
            ldm4(a[0], bA + ks * 32);
            ldm4(a[1], bA + 16 * BPAD + ks * 32);
#pragma unroll
            for (int p = 0; p < 4; p++) ldm4(b[p], bB + p * 16 * BPAD + ks * 32);
#pragma unroll
            for (int mt = 0; mt < 2; mt++)
#pragma unroll
                for (int nt = 0; nt < 8; nt++)
                    mma_f16(acc[mt][nt], a[mt], &b[nt >> 1][(nt & 1) * 2]);
        }
    };

    // ---- prologue: chunk 0 ----
    loadB(0);
    cpA(0, 0);
    CP_COMMIT();
    storeB(0);
    CP_WAIT0();
    __syncthreads();

    // ---- main loop: one barrier per chunk ----
    for (int c = 0; c < nchunks; c++) {
        const int st = c & 1;
        const bool more = (c + 1 < nchunks);
        if (more) {
            cpA(c + 1, st ^ 1);
            CP_COMMIT();
            loadB(c + 1);          // LDG early, hidden under compute
        }
        compute(st);
        if (more) storeB(st ^ 1);  // convert+STS after compute
        CP_WAIT0();
        __syncthreads();
    }

    // ---- epilogue ----
    const int qr = lane >> 2, qc = (lane & 3) * 2;
#pragma unroll
    for (int mt = 0; mt < 2; mt++) {
        const int row = wm * 32 + mt * 16 + qr;
#pragma unroll
        for (int nt = 0; nt < 8; nt++) {
            const int col = n0 + wn * 64 + nt * 8 + qc;
            float2 v0; v0.x = acc[mt][nt][0]; v0.y = acc[mt][nt][1];
            float2 v1; v1.x = acc[mt][nt][2]; v1.y = acc[mt][nt][3];
            *(float2*)(out + (size_t)row * NQ + col) = v0;
            *(float2*)(out + (size_t)(row + 8) * NQ + col) = v1;
        }
    }
}

// ---------------- per-row reduction: 2 blocks per row (half-Q each) ----------------
__global__ __launch_bounds__(256) void row_reduce(
    const float* __restrict__ old_embeds, const float* __restrict__ feat_queue,
    const int* __restrict__ labels, const int* __restrict__ hdrp)
{
    const int i = blockIdx.x >> 1, half = blockIdx.x & 1, tid = threadIdx.x;
    const int lbl = labels[i];
    const int hdr = *hdrp;
    const int j0 = half * (NQ / 2);
    const float4* s1r = (const float4*)(g_s1 + (size_t)i * NQ + j0);
    const float4* s2r = (const float4*)(g_s2 + (size_t)i * NQ + j0);
    const int4*   ql4 = (const int4*)(g_qlab + j0);
    const float* oei = old_embeds + (size_t)i * DDIM;
    constexpr int NV = (NQ / 2) / 4;

    float m1 = -INFINITY, m2 = -INFINITY;
    for (int v = tid; v < NV; v += 256) {
        float4 a = s1r[v], b = s2r[v];
        m1 = fmaxf(fmaxf(fmaxf(m1, a.x), fmaxf(a.y, a.z)), a.w);
        m2 = fmaxf(fmaxf(fmaxf(m2, b.x), fmaxf(b.y, b.z)), b.w);
    }
    for (int o = 16; o; o >>= 1) {
        m1 = fmaxf(m1, __shfl_xor_sync(0xffffffffu, m1, o));
        m2 = fmaxf(m2, __shfl_xor_sync(0xffffffffu, m2, o));
    }
    __shared__ float shm1[8], shm2[8];
    if ((tid & 31) == 0) { shm1[tid >> 5] = m1; shm2[tid >> 5] = m2; }
    __syncthreads();
    float M1 = shm1[0], M2 = shm2[0];
    for (int w = 1; w < 8; w++) { M1 = fmaxf(M1, shm1[w]); M2 = fmaxf(M2, shm2[w]); }

    float l1 = 0.f, l2 = 0.f, sw = 0.f, s1w = 0.f, s2w = 0.f, cnt = 0.f;
    for (int v = tid; v < NV; v += 256) {
        float4 a = s1r[v], b = s2r[v];
        l1 += __expf(a.x - M1) + __expf(a.y - M1) + __expf(a.z - M1) + __expf(a.w - M1);
        l2 += __expf(b.x - M2) + __expf(b.y - M2) + __expf(b.z - M2) + __expf(b.w - M2);
        int4 q = ql4[v];
        if (q.x == lbl || q.y == lbl || q.z == lbl || q.w == lbl) {
            const float va[4] = {a.x, a.y, a.z, a.w};
            const float vb[4] = {b.x, b.y, b.z, b.w};
            const int   qq[4] = {q.x, q.y, q.z, q.w};
#pragma unroll
            for (int e = 0; e < 4; e++) {
                if (qq[e] != lbl) continue;
                int jj = j0 + v * 4 + e;
                int r = (jj - hdr) & (NQ - 1);
                const float* frow = (r < NROW) ? (old_embeds + (size_t)r * DDIM)
                                               : (feat_queue + (size_t)jj * DDIM);
                float dot = 0.f;
#pragma unroll 8
                for (int d = 0; d < DDIM; d++) dot = fmaf(oei[d], frow[d], dot);
                float w = 0.5f * (dot + 1.0f);
                sw += w; s1w += w * va[e]; s2w += w * vb[e]; cnt += 1.f;
            }
        }
    }
    for (int o = 16; o; o >>= 1) {
        l1  += __shfl_down_sync(0xffffffffu, l1, o);
        l2  += __shfl_down_sync(0xffffffffu, l2, o);
        sw  += __shfl_down_sync(0xffffffffu, sw, o);
        s1w += __shfl_down_sync(0xffffffffu, s1w, o);
        s2w += __shfl_down_sync(0xffffffffu, s2w, o);
        cnt += __shfl_down_sync(0xffffffffu, cnt, o);
    }
    __shared__ float shl1[8], shl2[8], shsw[8], shs1[8], shs2[8], shc[8];
    if ((tid & 31) == 0) {
        int w = tid >> 5;
        shl1[w] = l1; shl2[w] = l2; shsw[w] = sw; shs1[w] = s1w; shs2[w] = s2w; shc[w] = cnt;
    }
    __syncthreads();
    if (tid == 0) {
        float L1 = 0, L2 = 0, SW = 0, S1 = 0, S2 = 0, CN = 0;
        for (int w = 0; w < 8; w++) {
            L1 += shl1[w]; L2 += shl2[w]; SW += shsw[w];
            S1 += shs1[w]; S2 += shs2[w]; CN += shc[w];
        }
        float* p = g_part + blockIdx.x * 8;
        p[0] = M1; p[1] = L1; p[2] = M2; p[3] = L2;
        p[4] = SW; p[5] = S1; p[6] = S2; p[7] = CN;
    }
}

// ---------------- finalize ----------------
__global__ void finalize(float* __restrict__ out) {
    int tid = threadIdx.x;   // 128 threads, one row each
    const float* pa = g_part + (2 * tid) * 8;
    const float* pb = g_part + (2 * tid + 1) * 8;
    float M1 = fmaxf(pa[0], pb[0]);
    float L1 = pa[1] * __expf(pa[0] - M1) + pb[1] * __expf(pb[0] - M1);
    float M2 = fmaxf(pa[2], pb[2]);
    float L2 = pa[3] * __expf(pa[2] - M2) + pb[3] * __expf(pb[2] - M2);
    float SW = pa[4] + pb[4];
    float S1 = pa[5] + pb[5];
    float S2 = pa[6] + pb[6];
    float CN = pa[7] + pb[7];
    float lse1 = M1 + logf(L1);
    float lse2 = M2 + logf(L2);
    float ic = 1.0f / CN;
    float t1 = (S1 - lse1 * SW) * ic;
    float t2 = (S2 - lse2 * SW) * ic;
    for (int o = 16; o; o >>= 1) {
        t1 += __shfl_down_sync(0xffffffffu, t1, o);
        t2 += __shfl_down_sync(0xffffffffu, t2, o);
    }
    __shared__ float sh1[4], sh2[4];
    if ((tid & 31) == 0) { sh1[tid >> 5] = t1; sh2[tid >> 5] = t2; }
    __syncthreads();
    if (tid == 0) {
        out[0] = -(sh1[0] + sh1[1] + sh1[2] + sh1[3]) / (float)NROW;
        out[1] = -(sh2[0] + sh2[1] + sh2[2] + sh2[3]) / (float)NROW;
    }
}

// ---------------- launch ----------------
extern "C" void kernel_launch(void* const* d_in, const int* in_sizes, int n_in,
                              void* d_out, int out_size) {
    const float* old_embeds   = (const float*)d_in[0];
    const float* old_logits   = (const float*)d_in[1];
    const float* new_embeds   = (const float*)d_in[2];
    const float* new_logits   = (const float*)d_in[3];
    const int*   labels       = (const int*)d_in[4];
    const float* feat_queue   = (const float*)d_in[5];
    const float* logit_queue  = (const float*)d_in[6];
    const int*   queue_labels = (const int*)d_in[7];
    const int*   header       = (const int*)d_in[8];
    float* out = (float*)d_out;

    unsigned short *p_a1, *p_a2;
    float *p_s1, *p_s2;
    cudaGetSymbolAddress((void**)&p_a1, g_a1);
    cudaGetSymbolAddress((void**)&p_a2, g_a2);
    cudaGetSymbolAddress((void**)&p_s1, g_s1);
    cudaGetSymbolAddress((void**)&p_s2, g_s2);

    cudaFuncSetAttribute(gemm_mma, cudaFuncAttributeMaxDynamicSharedMemorySize, GEMM_SMEM);

    normalize_half<<<NROW, 128>>>(new_embeds);
    half_logits<<<(NROW * CDIM) / (256 * 4), 256>>>(new_logits);
    build_qlab<<<NQ / 256, 256>>>(queue_labels, labels, header);

    gemm_mma<<<NQ / 128, 256, GEMM_SMEM>>>(p_a1, feat_queue, old_embeds,
                                           header, p_s1, DDIM);
    gemm_mma<<<NQ / 128, 256, GEMM_SMEM>>>(p_a2, logit_queue, old_logits,
                                           header, p_s2, CDIM);

    row_reduce<<<2 * NROW, 256>>>(old_embeds, feat_queue, labels, header);
    finalize<<<1, 128>>>(out);
}